// round 5
// baseline (speedup 1.0000x reference)
#include <cuda_runtime.h>
#include <cuda_bf16.h>

#define K     2048
#define NROW  512
#define NT    128          // threads per CTA
#define CW    32           // window size
#define NCH   64           // K / CW
#define DW    64           // warmup depth
#define PADB  64           // ab pad on each side (== DW)
#define NEGF  (-1.0e4f)

#define SMEM_BYTES 50944
// smem map (bytes):
//   bet : float4[2080] @ 0       (33280)  beta_{t+1}; emit aliases Le into .x
//   abp : float2[2208] @ 33280   (17664)  branch metrics, padded [-64, K+64)
// chunk layout: element (w, c) at [w*stride + c]; abp stride 69, bet stride 65.

__device__ float2 g_P1[NROW * K];   // (y1+y2, y1-y2)  natural order
__device__ float2 g_P2[NROW * K];   // (y1i+y3, y1i-y3) interleaved order

// ---------------------------------------------------------------------------
// One sliding-window max-log BCJR pass. On entry abp holds branch metrics
// (a,b) for all t (La already folded in). On exit bet[.x] holds extrinsic
// Le[t] = LLR - (a+b)  (full LLR if FIN). No trailing sync.
// ---------------------------------------------------------------------------
template<bool FIN>
__device__ __forceinline__ void bcjr(float2* __restrict__ abp,
                                     float4* __restrict__ bet, int tid)
{
    float a0, a1, a2, a3;
    if (tid < NCH) {
        // forward warmup: ts in [tid*32, tid*32+64) = chunks {tid, tid+1}
        float ini = (tid < 3) ? NEGF : 0.0f;
        a0 = 0.0f; a1 = ini; a2 = ini; a3 = ini;
        const float2* p = abp + tid;
        #pragma unroll
        for (int half = 0; half < 2; half++) {
            #pragma unroll 8
            for (int w = 0; w < 32; w++) {
                float2 gg = p[w * 69];
                float n0 = fmaxf(a0 - gg.x, a1 + gg.x);
                float n2 = fmaxf(a0 + gg.x, a1 - gg.x);
                float n1 = fmaxf(a2 + gg.y, a3 - gg.y);
                float n3 = fmaxf(a2 - gg.y, a3 + gg.y);
                a0 = n0; a1 = n1; a2 = n2; a3 = n3;
                if ((w & 7) == 7) { a1 -= a0; a2 -= a0; a3 -= a0; a0 = 0.0f; }
            }
            p += 1;
        }
    } else {
        // backward warmup: ts descending over chunks {j+4, j+3}
        int j = tid - NCH;
        float b0 = 0.0f, b1 = 0.0f, b2 = 0.0f, b3 = 0.0f;
        const float2* p = abp + (j + 4);
        #pragma unroll
        for (int half = 0; half < 2; half++) {
            #pragma unroll 8
            for (int w = 31; w >= 0; w--) {
                float2 gg = p[w * 69];
                float n0 = fmaxf(b0 - gg.x, b2 + gg.x);
                float n1 = fmaxf(b2 - gg.x, b0 + gg.x);
                float n2 = fmaxf(b3 - gg.y, b1 + gg.y);
                float n3 = fmaxf(b1 - gg.y, b3 + gg.y);
                b0 = n0; b1 = n1; b2 = n2; b3 = n3;
                if ((w & 7) == 0) { b1 -= b0; b2 -= b0; b3 -= b0; b0 = 0.0f; }
            }
            p -= 1;
        }
        // store pass: t descending in chunk j (abp chunk j+2)
        const float2* q = abp + (j + 2);
        float4* pb = bet + j;
        #pragma unroll 8
        for (int w = 31; w >= 0; w--) {
            pb[w * 65] = make_float4(b0, b1, b2, b3);   // beta_{t+1}
            float2 gg = q[w * 69];
            float n0 = fmaxf(b0 - gg.x, b2 + gg.x);
            float n1 = fmaxf(b2 - gg.x, b0 + gg.x);
            float n2 = fmaxf(b3 - gg.y, b1 + gg.y);
            float n3 = fmaxf(b1 - gg.y, b3 + gg.y);
            b0 = n0; b1 = n1; b2 = n2; b3 = n3;
            if ((w & 7) == 0) { b1 -= b0; b2 -= b0; b3 -= b0; b0 = 0.0f; }
        }
    }
    __syncthreads();

    // forward emit: chunk tid (bet), chunk tid+2 (abp)
    if (tid < NCH) {
        const float2* q = abp + (tid + 2);
        float4* pb = bet + tid;
        #pragma unroll 8
        for (int w = 0; w < 32; w++) {
            float2 gg = q[w * 69];
            float4 Bv = pb[w * 65];
            float u0 = a0 - gg.x, u1 = a1 + gg.x;
            float u2 = a0 + gg.x, u3 = a1 - gg.x;
            float v1 = a2 + gg.y, v2 = a3 - gg.y;
            float v3 = a2 - gg.y, v4 = a3 + gg.y;
            // u=1 branches: s0->2(+a), s1->0(+a), s2->1(+b), s3->3(+b)
            float m1 = fmaxf(fmaxf(u2 + Bv.z, u1 + Bv.x),
                             fmaxf(v1 + Bv.y, v4 + Bv.w));
            // u=0 branches: s0->0(-a), s1->2(-a), s2->3(-b), s3->1(-b)
            float m0 = fmaxf(fmaxf(u0 + Bv.x, u3 + Bv.z),
                             fmaxf(v3 + Bv.w, v2 + Bv.y));
            float llr = m1 - m0;
            pb[w * 65].x = FIN ? llr : (llr - gg.x - gg.y);
            a0 = fmaxf(u0, u1); a2 = fmaxf(u2, u3);
            a1 = fmaxf(v1, v2); a3 = fmaxf(v3, v4);
            if ((w & 7) == 7) { a1 -= a0; a2 -= a0; a3 -= a0; a0 = 0.0f; }
        }
    }
}

// ---------------------------------------------------------------------------
// Fused kernel: encode + channel prep + 6 turbo iterations. One CTA per row.
// ---------------------------------------------------------------------------
__global__ __launch_bounds__(NT, 4) void turbo_kernel(
    const int* __restrict__ x, const float* __restrict__ n1,
    const float* __restrict__ n2, const float* __restrict__ n3,
    const int* __restrict__ perm, float* __restrict__ out)
{
    extern __shared__ char smraw[];
    float4* bet = (float4*)(smraw);
    float2* abp = (float2*)(smraw + 33280);
    // prep scratch (inside bet region, dead before first BCJR writes bet)
    float*    Y1  = (float*)smraw;                    // [2048]
    unsigned* xb  = (unsigned*)(smraw + 8192);        // [64]
    unsigned* xib = (unsigned*)(smraw + 8448);        // [64]
    unsigned (*pw)[64]  = (unsigned(*)[64])(smraw + 8704);
    unsigned (*cst)[64] = (unsigned(*)[64])(smraw + 9216);
    unsigned (*ent)[64] = (unsigned(*)[64])(smraw + 9728);

    const int row = blockIdx.x, tid = threadIdx.x;
    const int base = row * K;
    const int ibase = (tid & 31) * 69 + (tid >> 5) + 2;  // abp slot of t=tid+128k (+4k)
    const int lbase = (tid & 31) * 65 + (tid >> 5);      // bet slot of t=tid+128k (+4k)

    int permr[K / NT];
    #pragma unroll
    for (int k = 0; k < K / NT; k++) permr[k] = perm[tid + k * NT];

    // ---- ab pads: chunks 0,1 (fwd, -inf-like) and 66,67 (bwd, zeros) ----
    if (tid < PADB) {
        abp[(tid & 31) * 69 + (tid >> 5)] = make_float2(NEGF, NEGF);
        abp[(tid & 31) * 69 + (tid >> 5) + 66] = make_float2(0.0f, 0.0f);
    }

    // ---- encode: pack bits ----
    #pragma unroll
    for (int k = 0; k < K / NT; k++) {
        int t = tid + k * NT;
        unsigned bal = __ballot_sync(0xffffffffu, x[base + t] & 1);
        if ((tid & 31) == 0) xb[t >> 5] = bal;
    }
    __syncthreads();
    #pragma unroll
    for (int k = 0; k < K / NT; k++) {
        int i = tid + k * NT;
        int p = permr[k];
        int bit = (xb[p >> 5] >> (p & 31)) & 1;
        unsigned bal = __ballot_sync(0xffffffffu, bit);
        if ((tid & 31) == 0) xib[i >> 5] = bal;
    }
    __syncthreads();

    // chunk encode from zero state (2 sequences x 64 chunks)
    {
        int seq = tid >> 6, j = tid & 63;
        unsigned bits = seq ? xib[j] : xb[j];
        unsigned s1 = 0, s2 = 0, p = 0;
        #pragma unroll
        for (int i = 0; i < 32; i++) {
            unsigned u = (bits >> i) & 1u;
            unsigned a = u ^ s1 ^ s2;
            p |= (a ^ s2) << i;
            s2 = s1; s1 = a;
        }
        pw[seq][j]  = p;
        cst[seq][j] = (s1 << 1) | s2;
    }
    __syncthreads();
    if (tid < 2) {  // entry-state scan (M^3 = I)
        unsigned e1 = 0, e2 = 0;
        for (int j = 0; j < 64; j++) {
            ent[tid][j] = (e1 << 1) | e2;
            unsigned c = cst[tid][j];
            unsigned ne1 = e2 ^ ((c >> 1) & 1u);
            unsigned ne2 = (e1 ^ e2) ^ (c & 1u);
            e1 = ne1; e2 = ne2;
        }
    }
    __syncthreads();
    {   // parity correction by entry state
        int seq = tid >> 6, j = tid & 63;
        unsigned e = ent[seq][j];
        unsigned e1 = (e >> 1) & 1u, e2 = e & 1u;
        unsigned corr = (e1 ? 0x49249249u : 0u)
                      ^ ((e1 ^ e2) ? 0x92492492u : 0u)
                      ^ (e2 ? 0x24924924u : 0u);
        pw[seq][j] ^= corr;
    }
    __syncthreads();

    // ---- channel combinations; also fill abp for BCJR 1 (La = 0) ----
    #pragma unroll
    for (int k = 0; k < K / NT; k++) {
        int t = tid + k * NT;
        float xv = (float)(2 * (int)((xb[t >> 5] >> (t & 31)) & 1u) - 1);
        float pv = (float)(2 * (int)((pw[0][t >> 5] >> (t & 31)) & 1u) - 1);
        float y1 = xv + n1[base + t];
        float y2 = pv + n2[base + t];
        Y1[t] = y1;
        float2 sd = make_float2(y1 + y2, y1 - y2);
        g_P1[base + t] = sd;
        abp[ibase + 4 * k] = sd;
    }
    __syncthreads();
    #pragma unroll
    for (int k = 0; k < K / NT; k++) {
        int i = tid + k * NT;
        float y1i = Y1[permr[k]];
        float pv = (float)(2 * (int)((pw[1][i >> 5] >> (i & 31)) & 1u) - 1);
        float y3 = pv + n3[base + i];
        g_P2[base + i] = make_float2(y1i + y3, y1i - y3);
    }
    __syncthreads();

    const float2* gP1 = g_P1 + base;
    const float2* gP2 = g_P2 + base;

    // ---- 6 turbo iterations ----
    #pragma unroll 1
    for (int it = 0; it < 5; it++) {
        bcjr<false>(abp, bet, tid);
        __syncthreads();
        #pragma unroll
        for (int k = 0; k < K / NT; k++) {   // abp <- gP2 + Le1[perm]/2
            int pm = permr[k];
            float la = 0.5f * bet[(pm & 31) * 65 + (pm >> 5)].x;
            float2 sd = gP2[tid + k * NT];
            abp[ibase + 4 * k] = make_float2(sd.x + la, sd.y + la);
        }
        __syncthreads();
        bcjr<false>(abp, bet, tid);
        __syncthreads();
        #pragma unroll
        for (int k = 0; k < K / NT; k++) {   // abp[perm] <- gP1[perm] + Le2/2
            int pm = permr[k];
            float la = 0.5f * bet[lbase + 4 * k].x;
            float2 sd = gP1[pm];
            abp[(pm & 31) * 69 + (pm >> 5) + 2] = make_float2(sd.x + la, sd.y + la);
        }
        __syncthreads();
    }
    bcjr<false>(abp, bet, tid);
    __syncthreads();
    #pragma unroll
    for (int k = 0; k < K / NT; k++) {
        int pm = permr[k];
        float la = 0.5f * bet[(pm & 31) * 65 + (pm >> 5)].x;
        float2 sd = gP2[tid + k * NT];
        abp[ibase + 4 * k] = make_float2(sd.x + la, sd.y + la);
    }
    __syncthreads();
    bcjr<true>(abp, bet, tid);
    __syncthreads();

    float* orow = out + base;
    #pragma unroll
    for (int k = 0; k < K / NT; k++) {       // out[perm[i]] = L2[i]
        orow[permr[k]] = bet[lbase + 4 * k].x;
    }
}

// ---------------------------------------------------------------------------
extern "C" void kernel_launch(void* const* d_in, const int* in_sizes, int n_in,
                              void* d_out, int out_size)
{
    const int*   x    = (const int*)  d_in[0];
    const float* n1   = (const float*)d_in[1];
    const float* n2   = (const float*)d_in[2];
    const float* n3   = (const float*)d_in[3];
    const int*   perm = (const int*)  d_in[4];
    float* out = (float*)d_out;

    cudaFuncSetAttribute(turbo_kernel,
                         cudaFuncAttributeMaxDynamicSharedMemorySize, SMEM_BYTES);
    turbo_kernel<<<NROW, NT, SMEM_BYTES>>>(x, n1, n2, n3, perm, out);
}